// round 2
// baseline (speedup 1.0000x reference)
#include <cuda_runtime.h>
#include <cuda_bf16.h>

#define TT 512
#define H 8

typedef unsigned long long u64;

__device__ __forceinline__ float ex2f(float x) {
    float y; asm("ex2.approx.f32 %0, %1;" : "=f"(y) : "f"(x)); return y;
}
__device__ __forceinline__ float rcpf(float x) {
    float y; asm("rcp.approx.f32 %0, %1;" : "=f"(y) : "f"(x)); return y;
}
// a = -z*log2(e)  ->  sigmoid(z)
__device__ __forceinline__ float sigm_s(float a) { return rcpf(1.0f + ex2f(a)); }
// a = -2*z*log2(e) ->  tanh(z)
__device__ __forceinline__ float tanh_s(float a) { return fmaf(2.0f, rcpf(1.0f + ex2f(a)), -1.0f); }

__device__ __forceinline__ u64 pack2(float lo, float hi) {
    u64 r; asm("mov.b64 %0, {%1, %2};" : "=l"(r) : "f"(lo), "f"(hi)); return r;
}
__device__ __forceinline__ void unpack2(u64 v, float& lo, float& hi) {
    asm("mov.b64 {%0, %1}, %2;" : "=f"(lo), "=f"(hi) : "l"(v));
}
__device__ __forceinline__ u64 fma2(u64 a, u64 b, u64 c) {
    u64 r; asm("fma.rn.f32x2 %0, %1, %2, %3;" : "=l"(r) : "l"(a), "l"(b), "l"(c)); return r;
}
__device__ __forceinline__ u64 add2(u64 a, u64 b) {
    u64 r; asm("add.rn.f32x2 %0, %1, %2;" : "=l"(r) : "l"(a), "l"(b)); return r;
}
__device__ __forceinline__ float hsum2(u64 v) {
    float lo, hi; unpack2(v, lo, hi); return lo + hi;
}

__global__ void __launch_bounds__(32, 8)
lstm2_kernel(const float* __restrict__ x,
             const float* __restrict__ W_ih1, const float* __restrict__ W_hh1,
             const float* __restrict__ b_ih1, const float* __restrict__ b_hh1,
             const float* __restrict__ W_ih2, const float* __restrict__ W_hh2,
             const float* __restrict__ b_ih2, const float* __restrict__ b_hh2,
             const float* __restrict__ W_fc,  const float* __restrict__ b_fc,
             float* __restrict__ out)
{
    const int gtid  = blockIdx.x * blockDim.x + threadIdx.x;
    const int batch = gtid >> 3;
    const int n     = gtid & 7;
    const unsigned FULL = 0xffffffffu;

    const float NL  = -1.44269504088896340736f;   // -log2(e)   (sigmoid gates)
    const float N2L = -2.88539008177792681472f;   // -2*log2(e) (tanh gate)

    const int ri = n, rf = 8 + n, rg = 16 + n, ro = 24 + n;

    const float wxi = W_ih1[ri] * NL,  wxf = W_ih1[rf] * NL;
    const float wxg = W_ih1[rg] * N2L, wxo = W_ih1[ro] * NL;

    const u64 bi1 = pack2((b_ih1[ri] + b_hh1[ri]) * NL,  0.0f);
    const u64 bf1 = pack2((b_ih1[rf] + b_hh1[rf]) * NL,  0.0f);
    const u64 bg1 = pack2((b_ih1[rg] + b_hh1[rg]) * N2L, 0.0f);
    const u64 bo1 = pack2((b_ih1[ro] + b_hh1[ro]) * NL,  0.0f);
    const u64 bi2 = pack2((b_ih2[ri] + b_hh2[ri]) * NL,  0.0f);
    const u64 bf2 = pack2((b_ih2[rf] + b_hh2[rf]) * NL,  0.0f);
    const u64 bg2 = pack2((b_ih2[rg] + b_hh2[rg]) * N2L, 0.0f);
    const u64 bo2 = pack2((b_ih2[ro] + b_hh2[ro]) * NL,  0.0f);

    u64 whi1[4], whf1[4], whg1[4], who1[4];
    u64 wii2[4], wif2[4], wig2[4], wio2[4];
    u64 whi2[4], whf2[4], whg2[4], who2[4];
#pragma unroll
    for (int p = 0; p < 4; ++p) {
        const int k0 = 2*p, k1 = 2*p + 1;
        whi1[p] = pack2(W_hh1[ri*H + k0] * NL,  W_hh1[ri*H + k1] * NL);
        whf1[p] = pack2(W_hh1[rf*H + k0] * NL,  W_hh1[rf*H + k1] * NL);
        whg1[p] = pack2(W_hh1[rg*H + k0] * N2L, W_hh1[rg*H + k1] * N2L);
        who1[p] = pack2(W_hh1[ro*H + k0] * NL,  W_hh1[ro*H + k1] * NL);
        wii2[p] = pack2(W_ih2[ri*H + k0] * NL,  W_ih2[ri*H + k1] * NL);
        wif2[p] = pack2(W_ih2[rf*H + k0] * NL,  W_ih2[rf*H + k1] * NL);
        wig2[p] = pack2(W_ih2[rg*H + k0] * N2L, W_ih2[rg*H + k1] * N2L);
        wio2[p] = pack2(W_ih2[ro*H + k0] * NL,  W_ih2[ro*H + k1] * NL);
        whi2[p] = pack2(W_hh2[ri*H + k0] * NL,  W_hh2[ri*H + k1] * NL);
        whf2[p] = pack2(W_hh2[rf*H + k0] * NL,  W_hh2[rf*H + k1] * NL);
        whg2[p] = pack2(W_hh2[rg*H + k0] * N2L, W_hh2[rg*H + k1] * N2L);
        who2[p] = pack2(W_hh2[ro*H + k0] * NL,  W_hh2[ro*H + k1] * NL);
    }

    u64 h1[4], h2[4];
    const u64 Z = pack2(0.0f, 0.0f);
#pragma unroll
    for (int p = 0; p < 4; ++p) { h1[p] = Z; h2[p] = Z; }
    float c1 = 0.0f, c2 = 0.0f;

    const float4* __restrict__ xr = (const float4*)(x + (size_t)batch * TT);
    float4 cur = xr[0];

    for (int t4 = 0; t4 < TT/4; ++t4) {
        const int nidx = (t4 + 1 < TT/4) ? (t4 + 1) : t4;
        const float4 nxt = xr[nidx];

        float xs[4] = {cur.x, cur.y, cur.z, cur.w};
#pragma unroll
        for (int s = 0; s < 4; ++s) {
            const float xt = xs[s];

            // ---------- layer 1 ----------
            u64 vi = bi1, vf = bf1, vg = bg1, vo = bo1;
#pragma unroll
            for (int p = 0; p < 4; ++p) {
                vi = fma2(whi1[p], h1[p], vi);
                vf = fma2(whf1[p], h1[p], vf);
                vg = fma2(whg1[p], h1[p], vg);
                vo = fma2(who1[p], h1[p], vo);
            }
            const float ai = fmaf(wxi, xt, hsum2(vi));
            const float af = fmaf(wxf, xt, hsum2(vf));
            const float ag = fmaf(wxg, xt, hsum2(vg));
            const float ao = fmaf(wxo, xt, hsum2(vo));

            const float gi = sigm_s(ai);
            const float gf = sigm_s(af);
            const float go = sigm_s(ao);
            const float gg = tanh_s(ag);
            c1 = fmaf(gf, c1, gi * gg);
            const float h1n = go * tanh_s(c1 * N2L);

            {
                const float v0 = __shfl_sync(FULL, h1n, 0, 8);
                const float v1 = __shfl_sync(FULL, h1n, 1, 8);
                const float v2 = __shfl_sync(FULL, h1n, 2, 8);
                const float v3 = __shfl_sync(FULL, h1n, 3, 8);
                const float v4 = __shfl_sync(FULL, h1n, 4, 8);
                const float v5 = __shfl_sync(FULL, h1n, 5, 8);
                const float v6 = __shfl_sync(FULL, h1n, 6, 8);
                const float v7 = __shfl_sync(FULL, h1n, 7, 8);
                h1[0] = pack2(v0, v1); h1[1] = pack2(v2, v3);
                h1[2] = pack2(v4, v5); h1[3] = pack2(v6, v7);
            }

            // ---------- layer 2 ----------
            u64 ai2a = bi2, af2a = bf2, ag2a = bg2, ao2a = bo2;
            u64 ai2b = Z,   af2b = Z,   ag2b = Z,   ao2b = Z;
#pragma unroll
            for (int p = 0; p < 4; ++p) {
                ai2a = fma2(wii2[p], h1[p], ai2a);
                af2a = fma2(wif2[p], h1[p], af2a);
                ag2a = fma2(wig2[p], h1[p], ag2a);
                ao2a = fma2(wio2[p], h1[p], ao2a);
                ai2b = fma2(whi2[p], h2[p], ai2b);
                af2b = fma2(whf2[p], h2[p], af2b);
                ag2b = fma2(whg2[p], h2[p], ag2b);
                ao2b = fma2(who2[p], h2[p], ao2b);
            }
            const float a2i = hsum2(add2(ai2a, ai2b));
            const float a2f = hsum2(add2(af2a, af2b));
            const float a2g = hsum2(add2(ag2a, ag2b));
            const float a2o = hsum2(add2(ao2a, ao2b));

            const float g2i = sigm_s(a2i);
            const float g2f = sigm_s(a2f);
            const float g2o = sigm_s(a2o);
            const float g2g = tanh_s(a2g);
            c2 = fmaf(g2f, c2, g2i * g2g);
            const float h2n = g2o * tanh_s(c2 * N2L);

            {
                const float v0 = __shfl_sync(FULL, h2n, 0, 8);
                const float v1 = __shfl_sync(FULL, h2n, 1, 8);
                const float v2 = __shfl_sync(FULL, h2n, 2, 8);
                const float v3 = __shfl_sync(FULL, h2n, 3, 8);
                const float v4 = __shfl_sync(FULL, h2n, 4, 8);
                const float v5 = __shfl_sync(FULL, h2n, 5, 8);
                const float v6 = __shfl_sync(FULL, h2n, 6, 8);
                const float v7 = __shfl_sync(FULL, h2n, 7, 8);
                h2[0] = pack2(v0, v1); h2[1] = pack2(v2, v3);
                h2[2] = pack2(v4, v5); h2[3] = pack2(v6, v7);
            }
        }
        cur = nxt;
    }

    if (n < 4) {
        u64 acc = pack2(b_fc[n], 0.0f);
#pragma unroll
        for (int p = 0; p < 4; ++p) {
            const u64 w = pack2(W_fc[n*H + 2*p], W_fc[n*H + 2*p + 1]);
            acc = fma2(w, h2[p], acc);
        }
        out[batch * 4 + n] = hsum2(acc);
    }
}

extern "C" void kernel_launch(void* const* d_in, const int* in_sizes, int n_in,
                              void* d_out, int out_size)
{
    const float* x     = (const float*)d_in[0];
    const float* W_ih1 = (const float*)d_in[1];
    const float* W_hh1 = (const float*)d_in[2];
    const float* b_ih1 = (const float*)d_in[3];
    const float* b_hh1 = (const float*)d_in[4];
    const float* W_ih2 = (const float*)d_in[5];
    const float* W_hh2 = (const float*)d_in[6];
    const float* b_ih2 = (const float*)d_in[7];
    const float* b_hh2 = (const float*)d_in[8];
    const float* W_fc  = (const float*)d_in[9];
    const float* b_fc  = (const float*)d_in[10];
    float* out = (float*)d_out;

    const int B = in_sizes[0] / TT;          // 4096
    const int threads = 32;
    const int blocks  = (B * H) / threads;   // 1024

    lstm2_kernel<<<blocks, threads>>>(x, W_ih1, W_hh1, b_ih1, b_hh1,
                                      W_ih2, W_hh2, b_ih2, b_hh2,
                                      W_fc, b_fc, out);
}

// round 4
// speedup vs baseline: 1.4371x; 1.4371x over previous
#include <cuda_runtime.h>
#include <cuda_bf16.h>

#define TT 512
#define H 8

typedef unsigned long long u64;

__device__ __forceinline__ float tanhf_a(float x) {
    float y; asm("tanh.approx.f32 %0, %1;" : "=f"(y) : "f"(x)); return y;
}
__device__ __forceinline__ u64 pack2(float lo, float hi) {
    u64 r; asm("mov.b64 %0, {%1, %2};" : "=l"(r) : "f"(lo), "f"(hi)); return r;
}
__device__ __forceinline__ void unpack2(u64 v, float& lo, float& hi) {
    asm("mov.b64 {%0, %1}, %2;" : "=f"(lo), "=f"(hi) : "l"(v));
}
__device__ __forceinline__ u64 fma2(u64 a, u64 b, u64 c) {
    u64 r; asm("fma.rn.f32x2 %0, %1, %2, %3;" : "=l"(r) : "l"(a), "l"(b), "l"(c)); return r;
}
__device__ __forceinline__ u64 add2(u64 a, u64 b) {
    u64 r; asm("add.rn.f32x2 %0, %1, %2;" : "=l"(r) : "l"(a), "l"(b)); return r;
}
__device__ __forceinline__ float hsum2(u64 v) {
    float lo, hi; unpack2(v, lo, hi); return lo + hi;
}

__global__ void __launch_bounds__(128)
lstm2_kernel(const float* __restrict__ x,
             const float* __restrict__ W_ih1, const float* __restrict__ W_hh1,
             const float* __restrict__ b_ih1, const float* __restrict__ b_hh1,
             const float* __restrict__ W_ih2, const float* __restrict__ W_hh2,
             const float* __restrict__ b_ih2, const float* __restrict__ b_hh2,
             const float* __restrict__ W_fc,  const float* __restrict__ b_fc,
             float* __restrict__ out)
{
    const int gtid  = blockIdx.x * blockDim.x + threadIdx.x;
    const int batch = gtid >> 3;
    const int n     = gtid & 7;
    const unsigned FULL = 0xffffffffu;

    // sigmoid(z) = 0.5*tanh(0.5*z)+0.5  -> pre-scale sigmoid-gate weights by 0.5
    // tanh gate (g): plain tanh, scale 1.0
    const float SS = 0.5f, SG = 1.0f;

    // gate rows (PyTorch order i,f,g,o) for unit n
    const int ri = n, rf = 8 + n, rg = 16 + n, ro = 24 + n;

    // ---- layer-1 x weights (input dim = 1), pre-scaled ----
    const float wxi = W_ih1[ri] * SS, wxf = W_ih1[rf] * SS;
    const float wxg = W_ih1[rg] * SG, wxo = W_ih1[ro] * SS;

    // biases packed as (b, 0) to seed packed accumulator chains
    const u64 bi1 = pack2((b_ih1[ri] + b_hh1[ri]) * SS, 0.0f);
    const u64 bf1 = pack2((b_ih1[rf] + b_hh1[rf]) * SS, 0.0f);
    const u64 bg1 = pack2((b_ih1[rg] + b_hh1[rg]) * SG, 0.0f);
    const u64 bo1 = pack2((b_ih1[ro] + b_hh1[ro]) * SS, 0.0f);
    const u64 bi2 = pack2((b_ih2[ri] + b_hh2[ri]) * SS, 0.0f);
    const u64 bf2 = pack2((b_ih2[rf] + b_hh2[rf]) * SS, 0.0f);
    const u64 bg2 = pack2((b_ih2[rg] + b_hh2[rg]) * SG, 0.0f);
    const u64 bo2 = pack2((b_ih2[ro] + b_hh2[ro]) * SS, 0.0f);

    u64 whi1[4], whf1[4], whg1[4], who1[4];
    u64 wii2[4], wif2[4], wig2[4], wio2[4];
    u64 whi2[4], whf2[4], whg2[4], who2[4];
#pragma unroll
    for (int p = 0; p < 4; ++p) {
        const int k0 = 2*p, k1 = 2*p + 1;
        whi1[p] = pack2(W_hh1[ri*H + k0] * SS, W_hh1[ri*H + k1] * SS);
        whf1[p] = pack2(W_hh1[rf*H + k0] * SS, W_hh1[rf*H + k1] * SS);
        whg1[p] = pack2(W_hh1[rg*H + k0] * SG, W_hh1[rg*H + k1] * SG);
        who1[p] = pack2(W_hh1[ro*H + k0] * SS, W_hh1[ro*H + k1] * SS);
        wii2[p] = pack2(W_ih2[ri*H + k0] * SS, W_ih2[ri*H + k1] * SS);
        wif2[p] = pack2(W_ih2[rf*H + k0] * SS, W_ih2[rf*H + k1] * SS);
        wig2[p] = pack2(W_ih2[rg*H + k0] * SG, W_ih2[rg*H + k1] * SG);
        wio2[p] = pack2(W_ih2[ro*H + k0] * SS, W_ih2[ro*H + k1] * SS);
        whi2[p] = pack2(W_hh2[ri*H + k0] * SS, W_hh2[ri*H + k1] * SS);
        whf2[p] = pack2(W_hh2[rf*H + k0] * SS, W_hh2[rf*H + k1] * SS);
        whg2[p] = pack2(W_hh2[rg*H + k0] * SG, W_hh2[rg*H + k1] * SG);
        who2[p] = pack2(W_hh2[ro*H + k0] * SS, W_hh2[ro*H + k1] * SS);
    }

    u64 h1[4], h2[4];
    const u64 Z = pack2(0.0f, 0.0f);
#pragma unroll
    for (int p = 0; p < 4; ++p) { h1[p] = Z; h2[p] = Z; }
    float c1 = 0.0f, c2 = 0.0f;

    const float4* __restrict__ xr = (const float4*)(x + (size_t)batch * TT);
    float4 cur = xr[0];

    for (int t4 = 0; t4 < TT/4; ++t4) {
        const int nidx = (t4 + 1 < TT/4) ? (t4 + 1) : t4;
        const float4 nxt = xr[nidx];

        float xs[4] = {cur.x, cur.y, cur.z, cur.w};
#pragma unroll
        for (int s = 0; s < 4; ++s) {
            const float xt = xs[s];

            // ---------- layer 1 ----------
            u64 vi = bi1, vf = bf1, vg = bg1, vo = bo1;
#pragma unroll
            for (int p = 0; p < 4; ++p) {
                vi = fma2(whi1[p], h1[p], vi);
                vf = fma2(whf1[p], h1[p], vf);
                vg = fma2(whg1[p], h1[p], vg);
                vo = fma2(who1[p], h1[p], vo);
            }
            const float ai = fmaf(wxi, xt, hsum2(vi));
            const float af = fmaf(wxf, xt, hsum2(vf));
            const float ag = fmaf(wxg, xt, hsum2(vg));
            const float ao = fmaf(wxo, xt, hsum2(vo));

            const float gi = fmaf(0.5f, tanhf_a(ai), 0.5f);
            const float gf = fmaf(0.5f, tanhf_a(af), 0.5f);
            const float go = fmaf(0.5f, tanhf_a(ao), 0.5f);
            const float gg = tanhf_a(ag);
            c1 = fmaf(gf, c1, gi * gg);
            const float h1n = go * tanhf_a(c1);

            {
                const float v0 = __shfl_sync(FULL, h1n, 0, 8);
                const float v1 = __shfl_sync(FULL, h1n, 1, 8);
                const float v2 = __shfl_sync(FULL, h1n, 2, 8);
                const float v3 = __shfl_sync(FULL, h1n, 3, 8);
                const float v4 = __shfl_sync(FULL, h1n, 4, 8);
                const float v5 = __shfl_sync(FULL, h1n, 5, 8);
                const float v6 = __shfl_sync(FULL, h1n, 6, 8);
                const float v7 = __shfl_sync(FULL, h1n, 7, 8);
                h1[0] = pack2(v0, v1); h1[1] = pack2(v2, v3);
                h1[2] = pack2(v4, v5); h1[3] = pack2(v6, v7);
            }

            // ---------- layer 2 ----------
            u64 ai2a = bi2, af2a = bf2, ag2a = bg2, ao2a = bo2;
            u64 ai2b = Z,   af2b = Z,   ag2b = Z,   ao2b = Z;
#pragma unroll
            for (int p = 0; p < 4; ++p) {
                ai2a = fma2(wii2[p], h1[p], ai2a);
                af2a = fma2(wif2[p], h1[p], af2a);
                ag2a = fma2(wig2[p], h1[p], ag2a);
                ao2a = fma2(wio2[p], h1[p], ao2a);
                ai2b = fma2(whi2[p], h2[p], ai2b);
                af2b = fma2(whf2[p], h2[p], af2b);
                ag2b = fma2(whg2[p], h2[p], ag2b);
                ao2b = fma2(who2[p], h2[p], ao2b);
            }
            const float a2i = hsum2(add2(ai2a, ai2b));
            const float a2f = hsum2(add2(af2a, af2b));
            const float a2g = hsum2(add2(ag2a, ag2b));
            const float a2o = hsum2(add2(ao2a, ao2b));

            const float g2i = fmaf(0.5f, tanhf_a(a2i), 0.5f);
            const float g2f = fmaf(0.5f, tanhf_a(a2f), 0.5f);
            const float g2o = fmaf(0.5f, tanhf_a(a2o), 0.5f);
            const float g2g = tanhf_a(a2g);
            c2 = fmaf(g2f, c2, g2i * g2g);
            const float h2n = g2o * tanhf_a(c2);

            {
                const float v0 = __shfl_sync(FULL, h2n, 0, 8);
                const float v1 = __shfl_sync(FULL, h2n, 1, 8);
                const float v2 = __shfl_sync(FULL, h2n, 2, 8);
                const float v3 = __shfl_sync(FULL, h2n, 3, 8);
                const float v4 = __shfl_sync(FULL, h2n, 4, 8);
                const float v5 = __shfl_sync(FULL, h2n, 5, 8);
                const float v6 = __shfl_sync(FULL, h2n, 6, 8);
                const float v7 = __shfl_sync(FULL, h2n, 7, 8);
                h2[0] = pack2(v0, v1); h2[1] = pack2(v2, v3);
                h2[2] = pack2(v4, v5); h2[3] = pack2(v6, v7);
            }
        }
        cur = nxt;
    }

    // ---------- final FC (8 -> 4) ----------
    if (n < 4) {
        u64 acc = pack2(b_fc[n], 0.0f);
#pragma unroll
        for (int p = 0; p < 4; ++p) {
            const u64 w = pack2(W_fc[n*H + 2*p], W_fc[n*H + 2*p + 1]);
            acc = fma2(w, h2[p], acc);
        }
        out[batch * 4 + n] = hsum2(acc);
    }
}

extern "C" void kernel_launch(void* const* d_in, const int* in_sizes, int n_in,
                              void* d_out, int out_size)
{
    const float* x     = (const float*)d_in[0];
    const float* W_ih1 = (const float*)d_in[1];
    const float* W_hh1 = (const float*)d_in[2];
    const float* b_ih1 = (const float*)d_in[3];
    const float* b_hh1 = (const float*)d_in[4];
    const float* W_ih2 = (const float*)d_in[5];
    const float* W_hh2 = (const float*)d_in[6];
    const float* b_ih2 = (const float*)d_in[7];
    const float* b_hh2 = (const float*)d_in[8];
    const float* W_fc  = (const float*)d_in[9];
    const float* b_fc  = (const float*)d_in[10];
    float* out = (float*)d_out;

    const int B = in_sizes[0] / TT;          // 4096
    const int threads = 128;
    const int blocks  = (B * H) / threads;   // 256

    lstm2_kernel<<<blocks, threads>>>(x, W_ih1, W_hh1, b_ih1, b_hh1,
                                      W_ih2, W_hh2, b_ih2, b_hh2,
                                      W_fc, b_fc, out);
}

// round 5
// speedup vs baseline: 1.4963x; 1.0412x over previous
#include <cuda_runtime.h>
#include <cuda_bf16.h>

#define TT 512
#define H 8

typedef unsigned long long u64;

__device__ __forceinline__ float tanhf_a(float x) {
    float y; asm("tanh.approx.f32 %0, %1;" : "=f"(y) : "f"(x)); return y;
}
__device__ __forceinline__ u64 pack2(float lo, float hi) {
    u64 r; asm("mov.b64 %0, {%1, %2};" : "=l"(r) : "f"(lo), "f"(hi)); return r;
}
__device__ __forceinline__ void unpack2(u64 v, float& lo, float& hi) {
    asm("mov.b64 {%0, %1}, %2;" : "=f"(lo), "=f"(hi) : "l"(v));
}
__device__ __forceinline__ u64 fma2(u64 a, u64 b, u64 c) {
    u64 r; asm("fma.rn.f32x2 %0, %1, %2, %3;" : "=l"(r) : "l"(a), "l"(b), "l"(c)); return r;
}
__device__ __forceinline__ u64 add2(u64 a, u64 b) {
    u64 r; asm("add.rn.f32x2 %0, %1, %2;" : "=l"(r) : "l"(a), "l"(b)); return r;
}
__device__ __forceinline__ float hsum2(u64 v) {
    float lo, hi; unpack2(v, lo, hi); return lo + hi;
}

__global__ void __launch_bounds__(128)
lstm2_kernel(const float* __restrict__ x,
             const float* __restrict__ W_ih1, const float* __restrict__ W_hh1,
             const float* __restrict__ b_ih1, const float* __restrict__ b_hh1,
             const float* __restrict__ W_ih2, const float* __restrict__ W_hh2,
             const float* __restrict__ b_ih2, const float* __restrict__ b_hh2,
             const float* __restrict__ W_fc,  const float* __restrict__ b_fc,
             float* __restrict__ out)
{
    const int gtid  = blockIdx.x * blockDim.x + threadIdx.x;
    const int batch = gtid >> 3;
    const int n     = gtid & 7;
    const unsigned FULL = 0xffffffffu;

    // sigmoid(z) = 0.5*tanh(0.5*z)+0.5 -> pre-scale sigmoid-gate rows by 0.5
    const float SS = 0.5f, SG = 1.0f;
    const int ri = n, rf = 8 + n, rg = 16 + n, ro = 24 + n;

    // layer-1 x weights packed as (w, 0) so the x-term seeds the packed chain
    const u64 wxi2 = pack2(W_ih1[ri] * SS, 0.0f);
    const u64 wxf2 = pack2(W_ih1[rf] * SS, 0.0f);
    const u64 wxg2 = pack2(W_ih1[rg] * SG, 0.0f);
    const u64 wxo2 = pack2(W_ih1[ro] * SS, 0.0f);

    const u64 bi1 = pack2((b_ih1[ri] + b_hh1[ri]) * SS, 0.0f);
    const u64 bf1 = pack2((b_ih1[rf] + b_hh1[rf]) * SS, 0.0f);
    const u64 bg1 = pack2((b_ih1[rg] + b_hh1[rg]) * SG, 0.0f);
    const u64 bo1 = pack2((b_ih1[ro] + b_hh1[ro]) * SS, 0.0f);
    const u64 bi2 = pack2((b_ih2[ri] + b_hh2[ri]) * SS, 0.0f);
    const u64 bf2 = pack2((b_ih2[rf] + b_hh2[rf]) * SS, 0.0f);
    const u64 bg2 = pack2((b_ih2[rg] + b_hh2[rg]) * SG, 0.0f);
    const u64 bo2 = pack2((b_ih2[ro] + b_hh2[ro]) * SS, 0.0f);

    u64 whi1[4], whf1[4], whg1[4], who1[4];
    u64 wii2[4], wif2[4], wig2[4], wio2[4];
    u64 whi2[4], whf2[4], whg2[4], who2[4];
#pragma unroll
    for (int p = 0; p < 4; ++p) {
        const int k0 = 2*p, k1 = 2*p + 1;
        whi1[p] = pack2(W_hh1[ri*H + k0] * SS, W_hh1[ri*H + k1] * SS);
        whf1[p] = pack2(W_hh1[rf*H + k0] * SS, W_hh1[rf*H + k1] * SS);
        whg1[p] = pack2(W_hh1[rg*H + k0] * SG, W_hh1[rg*H + k1] * SG);
        who1[p] = pack2(W_hh1[ro*H + k0] * SS, W_hh1[ro*H + k1] * SS);
        wii2[p] = pack2(W_ih2[ri*H + k0] * SS, W_ih2[ri*H + k1] * SS);
        wif2[p] = pack2(W_ih2[rf*H + k0] * SS, W_ih2[rf*H + k1] * SS);
        wig2[p] = pack2(W_ih2[rg*H + k0] * SG, W_ih2[rg*H + k1] * SG);
        wio2[p] = pack2(W_ih2[ro*H + k0] * SS, W_ih2[ro*H + k1] * SS);
        whi2[p] = pack2(W_hh2[ri*H + k0] * SS, W_hh2[ri*H + k1] * SS);
        whf2[p] = pack2(W_hh2[rf*H + k0] * SS, W_hh2[rf*H + k1] * SS);
        whg2[p] = pack2(W_hh2[rg*H + k0] * SG, W_hh2[rg*H + k1] * SG);
        who2[p] = pack2(W_hh2[ro*H + k0] * SS, W_hh2[ro*H + k1] * SS);
    }

    const u64 Z = pack2(0.0f, 0.0f);
    u64 h1p[4], h2p[4];           // h1(t-1), h2(t-2) broadcasts (packed pairs)
#pragma unroll
    for (int p = 0; p < 4; ++p) { h1p[p] = Z; h2p[p] = Z; }
    float c1 = 0.0f, c2 = 0.0f;

    // One pipelined body: layer1(t) [uses h1p, xt] || layer2(t-1) [uses h1p, h2p]
    auto step = [&](float xt) {
        const u64 xt2 = pack2(xt, 0.0f);

        // ---- layer1(t): seed includes x-term, then 4-deep packed hh chain ----
        u64 vi = fma2(wxi2, xt2, bi1);
        u64 vf = fma2(wxf2, xt2, bf1);
        u64 vg = fma2(wxg2, xt2, bg1);
        u64 vo = fma2(wxo2, xt2, bo1);
        // ---- layer2(t-1): two 4-deep chains per gate ----
        u64 ai2a = bi2, af2a = bf2, ag2a = bg2, ao2a = bo2;
        u64 ai2b = Z,   af2b = Z,   ag2b = Z,   ao2b = Z;
#pragma unroll
        for (int p = 0; p < 4; ++p) {
            vi = fma2(whi1[p], h1p[p], vi);
            vf = fma2(whf1[p], h1p[p], vf);
            vg = fma2(whg1[p], h1p[p], vg);
            vo = fma2(who1[p], h1p[p], vo);
            ai2a = fma2(wii2[p], h1p[p], ai2a);
            af2a = fma2(wif2[p], h1p[p], af2a);
            ag2a = fma2(wig2[p], h1p[p], ag2a);
            ao2a = fma2(wio2[p], h1p[p], ao2a);
            ai2b = fma2(whi2[p], h2p[p], ai2b);
            af2b = fma2(whf2[p], h2p[p], af2b);
            ag2b = fma2(whg2[p], h2p[p], ag2b);
            ao2b = fma2(who2[p], h2p[p], ao2b);
        }
        const float ai = hsum2(vi);
        const float af = hsum2(vf);
        const float ag = hsum2(vg);
        const float ao = hsum2(vo);
        const float a2i = hsum2(add2(ai2a, ai2b));
        const float a2f = hsum2(add2(af2a, af2b));
        const float a2g = hsum2(add2(ag2a, ag2b));
        const float a2o = hsum2(add2(ao2a, ao2b));

        const float gi = fmaf(0.5f, tanhf_a(ai), 0.5f);
        const float gf = fmaf(0.5f, tanhf_a(af), 0.5f);
        const float go = fmaf(0.5f, tanhf_a(ao), 0.5f);
        const float gg = tanhf_a(ag);
        const float g2i = fmaf(0.5f, tanhf_a(a2i), 0.5f);
        const float g2f = fmaf(0.5f, tanhf_a(a2f), 0.5f);
        const float g2o = fmaf(0.5f, tanhf_a(a2o), 0.5f);
        const float g2g = tanhf_a(a2g);

        c1 = fmaf(gf, c1, gi * gg);
        c2 = fmaf(g2f, c2, g2i * g2g);
        const float h1n = go  * tanhf_a(c1);
        const float h2n = g2o * tanhf_a(c2);

        // 16 independent broadcasts, latencies overlapped
        const float a0 = __shfl_sync(FULL, h1n, 0, 8);
        const float a1 = __shfl_sync(FULL, h1n, 1, 8);
        const float a2 = __shfl_sync(FULL, h1n, 2, 8);
        const float a3 = __shfl_sync(FULL, h1n, 3, 8);
        const float a4 = __shfl_sync(FULL, h1n, 4, 8);
        const float a5 = __shfl_sync(FULL, h1n, 5, 8);
        const float a6 = __shfl_sync(FULL, h1n, 6, 8);
        const float a7 = __shfl_sync(FULL, h1n, 7, 8);
        const float b0 = __shfl_sync(FULL, h2n, 0, 8);
        const float b1 = __shfl_sync(FULL, h2n, 1, 8);
        const float b2 = __shfl_sync(FULL, h2n, 2, 8);
        const float b3 = __shfl_sync(FULL, h2n, 3, 8);
        const float b4 = __shfl_sync(FULL, h2n, 4, 8);
        const float b5 = __shfl_sync(FULL, h2n, 5, 8);
        const float b6 = __shfl_sync(FULL, h2n, 6, 8);
        const float b7 = __shfl_sync(FULL, h2n, 7, 8);
        h1p[0] = pack2(a0, a1); h1p[1] = pack2(a2, a3);
        h1p[2] = pack2(a4, a5); h1p[3] = pack2(a6, a7);
        h2p[0] = pack2(b0, b1); h2p[1] = pack2(b2, b3);
        h2p[2] = pack2(b4, b5); h2p[3] = pack2(b6, b7);
    };

    const float4* __restrict__ xr = (const float4*)(x + (size_t)batch * TT);
    float4 cur = xr[0];
    float4 nxt = xr[1];

    // prologue: body computes layer1(0); its layer2(-1) output is junk -> reset
    step(cur.x);
    c2 = 0.0f;
#pragma unroll
    for (int p = 0; p < 4; ++p) h2p[p] = Z;

    step(cur.y); step(cur.z); step(cur.w);
    cur = nxt;

    for (int t4 = 1; t4 < TT/4; ++t4) {
        const int nidx = (t4 + 1 < TT/4) ? (t4 + 1) : t4;
        nxt = xr[nidx];
        step(cur.x); step(cur.y); step(cur.z); step(cur.w);
        cur = nxt;
    }

    // epilogue: one more body computes layer2(511); its layer1(512) is discarded
    step(0.0f);

    // ---------- final FC (8 -> 4): h2p holds broadcast h2(511) ----------
    if (n < 4) {
        u64 acc = pack2(b_fc[n], 0.0f);
#pragma unroll
        for (int p = 0; p < 4; ++p) {
            const u64 w = pack2(W_fc[n*H + 2*p], W_fc[n*H + 2*p + 1]);
            acc = fma2(w, h2p[p], acc);
        }
        out[batch * 4 + n] = hsum2(acc);
    }
}

extern "C" void kernel_launch(void* const* d_in, const int* in_sizes, int n_in,
                              void* d_out, int out_size)
{
    const float* x     = (const float*)d_in[0];
    const float* W_ih1 = (const float*)d_in[1];
    const float* W_hh1 = (const float*)d_in[2];
    const float* b_ih1 = (const float*)d_in[3];
    const float* b_hh1 = (const float*)d_in[4];
    const float* W_ih2 = (const float*)d_in[5];
    const float* W_hh2 = (const float*)d_in[6];
    const float* b_ih2 = (const float*)d_in[7];
    const float* b_hh2 = (const float*)d_in[8];
    const float* W_fc  = (const float*)d_in[9];
    const float* b_fc  = (const float*)d_in[10];
    float* out = (float*)d_out;

    const int B = in_sizes[0] / TT;          // 4096
    const int threads = 128;
    const int blocks  = (B * H) / threads;   // 256

    lstm2_kernel<<<blocks, threads>>>(x, W_ih1, W_hh1, b_ih1, b_hh1,
                                      W_ih2, W_hh2, b_ih2, b_hh2,
                                      W_fc, b_fc, out);
}